// round 12
// baseline (speedup 1.0000x reference)
#include <cuda_runtime.h>
#include <cuda_bf16.h>
#include <cuda_fp8.h>
#include <cstdint>
#include <math.h>

// ============================================================================
// Problem constants
// ============================================================================

static constexpr int D_IN  = 1024;
static constexpr int D_OUT = 1024;
static constexpr int M_MAX = 32768;

static constexpr int TILE_M = 128;
static constexpr int TILE_N = 128;
static constexpr int KCH    = 128;              // K bytes per chunk
static constexpr int NCH    = D_IN / KCH;       // 8 chunks
static constexpr int STAGES = 3;
static constexpr int THREADS = 128;             // 4 warps: 2 (M) x 2 (N), 64x64

static constexpr int TILE_BYTES  = 128 * KCH;             // 16 KB per tile image
static constexpr int STAGE_BYTES = 2 * TILE_BYTES;        // A + B = 32 KB
static constexpr int SMEM_TILES  = 1024;                  // tiles start (1K-aligned)
static constexpr int SMEM_ALLOC  = SMEM_TILES + STAGES * STAGE_BYTES;  // 99328

// fused quant/prep kernel split
static constexpr int NQBLK = M_MAX / 8;                   // 4096 quant blocks
static constexpr int NPBLK = (D_OUT * D_IN / 4) / 256;    // 1024 prep blocks

#define SWZ(off) ((off) ^ (((off) >> 3) & 0x70))

// ============================================================================
// Scratch (device globals) — PRE-SWIZZLED tile-major layout:
//   g_qx: [M/128 groups][8 kchunks][16384 B tile image (SW128)]
//   g_qw: [8 ngroups   ][8 kchunks][16384 B tile image (SW128)]
// ============================================================================

__device__ __align__(16) unsigned char g_qx[(size_t)M_MAX * D_IN];
__device__ __align__(16) float g_xscale[M_MAX];
__device__ __align__(16) unsigned char g_qw[(size_t)D_OUT * D_IN];

// ============================================================================
// PTX wrappers (base compute_103-safe)
// ============================================================================

__device__ __forceinline__ uint32_t smem_to_u32(const void* smem_ptr) {
    uint32_t addr;
    asm("{ .reg .u64 tmp; cvta.to.shared.u64 tmp, %1; cvt.u32.u64 %0, tmp; }"
        : "=r"(addr) : "l"(smem_ptr));
    return addr;
}

__device__ __forceinline__ void bulk_g2s(uint32_t dst, const void* src,
                                         uint32_t bytes, uint32_t mbar) {
    asm volatile(
        "cp.async.bulk.shared::cluster.global.mbarrier::complete_tx::bytes "
        "[%0], [%1], %2, [%3];"
        :: "r"(dst), "l"(src), "r"(bytes), "r"(mbar) : "memory");
}

#define MBARRIER_INIT(mbar, count) \
    asm volatile("mbarrier.init.shared.b64 [%0], %1;" \
                 :: "r"((uint32_t)(mbar)), "r"((uint32_t)(count)) : "memory")

#define MBARRIER_EXPECT_TX(mbar, bytes) \
    asm volatile("mbarrier.arrive.expect_tx.shared.b64 _, [%0], %1;" \
                 :: "r"((uint32_t)(mbar)), "r"((uint32_t)(bytes)) : "memory")

#define MBARRIER_WAIT_PARITY(mbar, parity) do { \
    uint32_t _mbar = (uint32_t)(mbar); \
    uint32_t _par  = (uint32_t)(parity); \
    asm volatile( \
        "{\n\t" \
        ".reg .pred P1;\n\t" \
        "WAIT_LOOP_%=:\n\t" \
        "mbarrier.try_wait.parity.acquire.cta.shared::cta.b64 P1, [%0], %1, 0x989680;\n\t" \
        "@P1 bra.uni WAIT_DONE_%=;\n\t" \
        "bra.uni WAIT_LOOP_%=;\n\t" \
        "WAIT_DONE_%=:\n\t" \
        "}" \
        :: "r"(_mbar), "r"(_par) : "memory"); \
} while (0)

__device__ __forceinline__ void ldmatrix_x4(uint32_t* r, uint32_t addr) {
    asm volatile("ldmatrix.sync.aligned.m8n8.x4.shared.b16 {%0,%1,%2,%3}, [%4];"
                 : "=r"(r[0]), "=r"(r[1]), "=r"(r[2]), "=r"(r[3])
                 : "r"(addr));
}

__device__ __forceinline__ void mma_fp8(
    float d[4], const uint32_t a[4], const uint32_t b0, const uint32_t b1)
{
    asm volatile(
        "mma.sync.aligned.m16n8k32.row.col.f32.e4m3.e4m3.f32 "
        "{%0,%1,%2,%3}, {%4,%5,%6,%7}, {%8,%9}, {%0,%1,%2,%3};"
        : "+f"(d[0]), "+f"(d[1]), "+f"(d[2]), "+f"(d[3])
        : "r"(a[0]), "r"(a[1]), "r"(a[2]), "r"(a[3]),
          "r"(b0), "r"(b1));
}

// ============================================================================
// Kernel 1: FUSED quant + weight-prep (independent roles by block range)
//   bids [0, NQBLK)          : per-token fp8 quantization (8 tokens/block)
//   bids [NQBLK, NQBLK+NPBLK): weight conversion (per-block dtype detect)
// ============================================================================

__global__ void __launch_bounds__(256) fp8ld_prep_kernel(
    const float* __restrict__ x, const void* __restrict__ w, int M)
{
    if (blockIdx.x < NQBLK) {
        // ---------------- quant role ----------------
        int token = blockIdx.x * 8 + (threadIdx.x >> 5);
        int lane  = threadIdx.x & 31;
        if (token >= M) return;

        const float4* xp =
            reinterpret_cast<const float4*>(x + (size_t)token * D_IN);
        float4 v[8];
        float amax = 0.0f;
#pragma unroll
        for (int i = 0; i < 8; i++) {
            v[i] = xp[lane + 32 * i];
            amax = fmaxf(amax, fmaxf(fmaxf(fabsf(v[i].x), fabsf(v[i].y)),
                                     fmaxf(fabsf(v[i].z), fabsf(v[i].w))));
        }
#pragma unroll
        for (int off = 16; off > 0; off >>= 1)
            amax = fmaxf(amax, __shfl_xor_sync(0xFFFFFFFFu, amax, off));

        float amax_c = fmaxf(amax, 1e-12f);
        float inv = 448.0f / amax_c;
        if (lane == 0) g_xscale[token] = amax_c / 448.0f;

        int r  = token & 127;
        int tg = token >> 7;
        uint32_t off = (uint32_t)(r * 128 + ((4 * lane) ^ ((r & 7) * 16)));
#pragma unroll
        for (int i = 0; i < 8; i++) {
            float4 u = v[i];
            __nv_fp8x2_storage_t lo = __nv_cvt_float2_to_fp8x2(
                make_float2(u.x * inv, u.y * inv), __NV_SATFINITE, __NV_E4M3);
            __nv_fp8x2_storage_t hi = __nv_cvt_float2_to_fp8x2(
                make_float2(u.z * inv, u.w * inv), __NV_SATFINITE, __NV_E4M3);
            *reinterpret_cast<uint32_t*>(
                g_qx + ((size_t)tg * NCH + i) * TILE_BYTES + off) =
                (uint32_t)lo | ((uint32_t)hi << 16);
        }
        return;
    }

    // ---------------- weight prep role (with per-block dtype detect) -------
    __shared__ int cf, cb;
    if (threadIdx.x == 0) { cf = 0; cb = 0; }
    __syncthreads();
    {
        const float* wf = (const float*)w;
        const __nv_bfloat16* wb = (const __nv_bfloat16*)w;
        int okf = 0, okb = 0;
        for (int i = threadIdx.x; i < 2048; i += 256) {
            float v = wf[i];
            if (isfinite(v) && fabsf(v) <= 448.0f) okf++;
        }
        for (int i = threadIdx.x; i < 4096; i += 256) {
            float u = __bfloat162float(wb[i]);
            if (isfinite(u) && fabsf(u) <= 448.0f) okb++;
        }
        atomicAdd(&cf, okf);
        atomicAdd(&cb, okb);
    }
    __syncthreads();
    int mode = (cf >= 1946) ? 0 : ((cb >= 3891) ? 1 : 2);

    int i = (blockIdx.x - NQBLK) * 256 + threadIdx.x;   // quad index (4 vals)

    uchar4 q;
    if (mode == 0) {
        float4 v = ((const float4*)w)[i];
        __nv_fp8x2_storage_t lo = __nv_cvt_float2_to_fp8x2(
            make_float2(v.x, v.y), __NV_SATFINITE, __NV_E4M3);
        __nv_fp8x2_storage_t hi = __nv_cvt_float2_to_fp8x2(
            make_float2(v.z, v.w), __NV_SATFINITE, __NV_E4M3);
        q.x = (unsigned char)(lo & 0xFF); q.y = (unsigned char)(lo >> 8);
        q.z = (unsigned char)(hi & 0xFF); q.w = (unsigned char)(hi >> 8);
    } else if (mode == 1) {
        const __nv_bfloat162* wb = (const __nv_bfloat162*)w;
        __nv_bfloat162 p0 = wb[i * 2];
        __nv_bfloat162 p1 = wb[i * 2 + 1];
        __nv_fp8x2_storage_t lo = __nv_cvt_float2_to_fp8x2(
            make_float2(__bfloat162float(p0.x), __bfloat162float(p0.y)),
            __NV_SATFINITE, __NV_E4M3);
        __nv_fp8x2_storage_t hi = __nv_cvt_float2_to_fp8x2(
            make_float2(__bfloat162float(p1.x), __bfloat162float(p1.y)),
            __NV_SATFINITE, __NV_E4M3);
        q.x = (unsigned char)(lo & 0xFF); q.y = (unsigned char)(lo >> 8);
        q.z = (unsigned char)(hi & 0xFF); q.w = (unsigned char)(hi >> 8);
    } else {
        q = ((const uchar4*)w)[i];
    }

    // scatter into tile-major swizzled image
    int b  = i * 4;             // linear byte index in [D_OUT][D_IN]
    int n  = b >> 10;           // weight row
    int k  = b & 1023;
    int kc = k >> 7;
    int c  = k & 127;
    int r  = n & 127;
    int ng = n >> 7;
    uint32_t off = (uint32_t)(r * 128 + (c ^ ((r & 7) * 16)));
    *reinterpret_cast<uchar4*>(
        g_qw + ((size_t)ng * NCH + kc) * TILE_BYTES + off) = q;
}

// ============================================================================
// Kernel 2: fp8 GEMM — bulk-copy loader + mbarrier full barriers +
//   __syncthreads WAR protection (R9 structure), 4 warps (64x64),
//   3-stage pipeline, 2 CTAs/SM. A-fragment double-buffered in registers.
// ============================================================================

__global__ void __launch_bounds__(THREADS, 2) fp8ld_gemm_kernel(
    const float* __restrict__ wscale_p,
    const float* __restrict__ bias,
    float* __restrict__ out,
    int M)
{
    extern __shared__ char smem[];
    uint32_t sb = smem_to_u32(smem);
    uint32_t mb = sb;                    // 3 mbarriers at +0, +8, +16
    uint32_t tiles = sb + SMEM_TILES;
    int tid = threadIdx.x;
    int wid = tid >> 5;
    int L   = tid & 31;
    int wm  = wid >> 1;
    int wn  = wid & 1;
    int n0  = blockIdx.x * TILE_N;
    int m0  = blockIdx.y * TILE_M;
    int mg  = m0 >> 7;
    int ng  = n0 >> 7;

    if (tid == 0) {
#pragma unroll
        for (int s = 0; s < STAGES; s++) MBARRIER_INIT(mb + 8 * s, 1);
    }
    __syncthreads();

    // Prologue: issue chunks 0 and 1
    if (tid == 0) {
#pragma unroll
        for (int p = 0; p < 2; p++) {
            uint32_t m = mb + 8 * p;
            uint32_t dst = tiles + p * STAGE_BYTES;
            MBARRIER_EXPECT_TX(m, STAGE_BYTES);
            bulk_g2s(dst, g_qx + ((size_t)mg * NCH + p) * TILE_BYTES,
                     TILE_BYTES, m);
            bulk_g2s(dst + TILE_BYTES, g_qw + ((size_t)ng * NCH + p) * TILE_BYTES,
                     TILE_BYTES, m);
        }
    }

    float d[4][8][4];
#pragma unroll
    for (int i = 0; i < 4; i++)
#pragma unroll
        for (int j = 0; j < 8; j++)
#pragma unroll
            for (int r = 0; r < 4; r++) d[i][j][r] = 0.0f;

    uint32_t a_off = SWZ((uint32_t)(
        (wm * 64 + ((L >> 3) & 1) * 8 + (L & 7)) * KCH + (L >> 4) * 16));
    uint32_t b_off = SWZ((uint32_t)(
        (wn * 64 + (L >> 4) * 8 + (L & 7)) * KCH + ((L >> 3) & 1) * 16));

    int ph0 = 0, ph1 = 0, ph2 = 0;

#pragma unroll 1
    for (int kc = 0; kc < NCH; kc++) {
        int s = kc % STAGES;
        if      (s == 0) { MBARRIER_WAIT_PARITY(mb + 0,  ph0); ph0 ^= 1; }
        else if (s == 1) { MBARRIER_WAIT_PARITY(mb + 8,  ph1); ph1 ^= 1; }
        else             { MBARRIER_WAIT_PARITY(mb + 16, ph2); ph2 ^= 1; }
        // All threads past wait[kc] => all finished computing chunk kc-1,
        // so stage (kc+2)%3 == (kc-1)%3 is reusable after this barrier.
        __syncthreads();
        if (kc + 2 < NCH && tid == 0) {
            int s2 = (kc + 2) % STAGES;
            uint32_t m = mb + 8 * s2;
            uint32_t dst = tiles + s2 * STAGE_BYTES;
            MBARRIER_EXPECT_TX(m, STAGE_BYTES);
            bulk_g2s(dst, g_qx + ((size_t)mg * NCH + kc + 2) * TILE_BYTES,
                     TILE_BYTES, m);
            bulk_g2s(dst + TILE_BYTES,
                     g_qw + ((size_t)ng * NCH + kc + 2) * TILE_BYTES,
                     TILE_BYTES, m);
        }

        uint32_t a_base = tiles + s * STAGE_BYTES + a_off;
        uint32_t b_base = tiles + s * STAGE_BYTES + TILE_BYTES + b_off;

        // SWZ(x + ks*32) == SWZ(x) ^ (ks*32): ks*32 only touches bits [5:6].
#pragma unroll
        for (int ks = 0; ks < 4; ks++) {
            uint32_t kx = (uint32_t)(ks * 32);
            uint32_t bfr[4][4];
#pragma unroll
            for (int t = 0; t < 4; t++)
                ldmatrix_x4(bfr[t], (b_base + (uint32_t)(t * 16 * KCH)) ^ kx);

            // A double-buffer: prefetch a[i+1] before consuming a[i], so the
            // LDSM->MMA dependency has ~8 MMA issues of slack instead of 0.
            uint32_t a[2][4];
            ldmatrix_x4(a[0], a_base ^ kx);
#pragma unroll
            for (int i = 0; i < 4; i++) {
                int cur = i & 1;
                if (i < 3)
                    ldmatrix_x4(a[cur ^ 1],
                                (a_base + (uint32_t)((i + 1) * 16 * KCH)) ^ kx);
#pragma unroll
                for (int t = 0; t < 4; t++) {
                    mma_fp8(d[i][2 * t + 0], a[cur], bfr[t][0], bfr[t][1]);
                    mma_fp8(d[i][2 * t + 1], a[cur], bfr[t][2], bfr[t][3]);
                }
            }
        }
    }

    // Epilogue: out = d * x_scale[m] * w_scale + bias[n]
    float wsc = *wscale_p;
    int ncol0 = n0 + wn * 64;
#pragma unroll
    for (int i = 0; i < 4; i++) {
        int mlo = m0 + wm * 64 + i * 16 + (L >> 2);
        float xs0 = g_xscale[mlo]     * wsc;
        float xs1 = g_xscale[mlo + 8] * wsc;
        float* r0 = out + (size_t)mlo * D_OUT + ncol0;
        float* r1 = r0 + (size_t)8 * D_OUT;
#pragma unroll
        for (int j = 0; j < 8; j++) {
            int c = j * 8 + (L & 3) * 2;
            float b0 = bias[ncol0 + c];
            float b1 = bias[ncol0 + c + 1];
            float2 lo = make_float2(d[i][j][0] * xs0 + b0, d[i][j][1] * xs0 + b1);
            float2 hi = make_float2(d[i][j][2] * xs1 + b0, d[i][j][3] * xs1 + b1);
            *reinterpret_cast<float2*>(r0 + c) = lo;
            *reinterpret_cast<float2*>(r1 + c) = hi;
        }
    }
}

// ============================================================================
// Launch
// ============================================================================

extern "C" void kernel_launch(void* const* d_in, const int* in_sizes, int n_in,
                              void* d_out, int out_size)
{
    const float* x      = (const float*)d_in[0];
    const void*  weight = (const void*)d_in[1];   // dtype probed at runtime
    const float* wscale = (const float*)d_in[2];
    const float* bias   = (const float*)d_in[3];
    float*       out    = (float*)d_out;

    int M = in_sizes[0] / D_IN;   // 32768

    fp8ld_prep_kernel<<<NQBLK + NPBLK, 256>>>(x, weight, M);

    cudaFuncSetAttribute(fp8ld_gemm_kernel,
                         cudaFuncAttributeMaxDynamicSharedMemorySize, SMEM_ALLOC);
    dim3 grid(D_OUT / TILE_N, M / TILE_M);   // (8, 256)
    fp8ld_gemm_kernel<<<grid, THREADS, SMEM_ALLOC>>>(wscale, bias, out, M);
}

// round 13
// speedup vs baseline: 1.2175x; 1.2175x over previous
#include <cuda_runtime.h>
#include <cuda_bf16.h>
#include <cuda_fp8.h>
#include <cstdint>
#include <math.h>

// ============================================================================
// Problem constants
// ============================================================================

static constexpr int D_IN  = 1024;
static constexpr int D_OUT = 1024;
static constexpr int M_MAX = 32768;

static constexpr int TILE_M = 128;
static constexpr int TILE_N = 128;
static constexpr int KCH    = 128;              // K bytes per chunk
static constexpr int NCH    = D_IN / KCH;       // 8 chunks
static constexpr int STAGES = 3;
static constexpr int THREADS = 128;             // 4 warps: 2 (M) x 2 (N), 64x64

static constexpr int TILE_BYTES  = 128 * KCH;             // 16 KB per tile image
static constexpr int STAGE_BYTES = 2 * TILE_BYTES;        // A + B = 32 KB
static constexpr int SMEM_TILES  = 1024;                  // tiles start (1K-aligned)
static constexpr int SMEM_ALLOC  = SMEM_TILES + STAGES * STAGE_BYTES;  // 99328

// fused quant/prep kernel split
static constexpr int NQBLK = M_MAX / 8;                   // 4096 quant blocks
static constexpr int NPBLK = (D_OUT * D_IN / 4) / 256;    // 1024 prep blocks

#define SWZ(off) ((off) ^ (((off) >> 3) & 0x70))

// ============================================================================
// Scratch (device globals) — PRE-SWIZZLED tile-major layout:
//   g_qx: [M/128 groups][8 kchunks][16384 B tile image (SW128)]
//   g_qw: [8 ngroups   ][8 kchunks][16384 B tile image (SW128)]
// ============================================================================

__device__ __align__(16) unsigned char g_qx[(size_t)M_MAX * D_IN];
__device__ __align__(16) float g_xscale[M_MAX];
__device__ __align__(16) unsigned char g_qw[(size_t)D_OUT * D_IN];

// ============================================================================
// PTX wrappers (base compute_103-safe)
// ============================================================================

__device__ __forceinline__ uint32_t smem_to_u32(const void* smem_ptr) {
    uint32_t addr;
    asm("{ .reg .u64 tmp; cvta.to.shared.u64 tmp, %1; cvt.u32.u64 %0, tmp; }"
        : "=r"(addr) : "l"(smem_ptr));
    return addr;
}

__device__ __forceinline__ void bulk_g2s(uint32_t dst, const void* src,
                                         uint32_t bytes, uint32_t mbar) {
    asm volatile(
        "cp.async.bulk.shared::cluster.global.mbarrier::complete_tx::bytes "
        "[%0], [%1], %2, [%3];"
        :: "r"(dst), "l"(src), "r"(bytes), "r"(mbar) : "memory");
}

#define MBARRIER_INIT(mbar, count) \
    asm volatile("mbarrier.init.shared.b64 [%0], %1;" \
                 :: "r"((uint32_t)(mbar)), "r"((uint32_t)(count)) : "memory")

#define MBARRIER_EXPECT_TX(mbar, bytes) \
    asm volatile("mbarrier.arrive.expect_tx.shared.b64 _, [%0], %1;" \
                 :: "r"((uint32_t)(mbar)), "r"((uint32_t)(bytes)) : "memory")

#define MBARRIER_WAIT_PARITY(mbar, parity) do { \
    uint32_t _mbar = (uint32_t)(mbar); \
    uint32_t _par  = (uint32_t)(parity); \
    asm volatile( \
        "{\n\t" \
        ".reg .pred P1;\n\t" \
        "WAIT_LOOP_%=:\n\t" \
        "mbarrier.try_wait.parity.acquire.cta.shared::cta.b64 P1, [%0], %1, 0x989680;\n\t" \
        "@P1 bra.uni WAIT_DONE_%=;\n\t" \
        "bra.uni WAIT_LOOP_%=;\n\t" \
        "WAIT_DONE_%=:\n\t" \
        "}" \
        :: "r"(_mbar), "r"(_par) : "memory"); \
} while (0)

__device__ __forceinline__ void ldmatrix_x4(uint32_t* r, uint32_t addr) {
    asm volatile("ldmatrix.sync.aligned.m8n8.x4.shared.b16 {%0,%1,%2,%3}, [%4];"
                 : "=r"(r[0]), "=r"(r[1]), "=r"(r[2]), "=r"(r[3])
                 : "r"(addr));
}

__device__ __forceinline__ void mma_fp8(
    float d[4], const uint32_t a[4], const uint32_t b0, const uint32_t b1)
{
    asm volatile(
        "mma.sync.aligned.m16n8k32.row.col.f32.e4m3.e4m3.f32 "
        "{%0,%1,%2,%3}, {%4,%5,%6,%7}, {%8,%9}, {%0,%1,%2,%3};"
        : "+f"(d[0]), "+f"(d[1]), "+f"(d[2]), "+f"(d[3])
        : "r"(a[0]), "r"(a[1]), "r"(a[2]), "r"(a[3]),
          "r"(b0), "r"(b1));
}

// ============================================================================
// Kernel 1: FUSED quant + weight-prep (independent roles by block range)
//   bids [0, NQBLK)          : per-token fp8 quantization (8 tokens/block)
//   bids [NQBLK, NQBLK+NPBLK): weight conversion (per-block dtype detect)
// ============================================================================

__global__ void __launch_bounds__(256) fp8ld_prep_kernel(
    const float* __restrict__ x, const void* __restrict__ w, int M)
{
    if (blockIdx.x < NQBLK) {
        // ---------------- quant role ----------------
        int token = blockIdx.x * 8 + (threadIdx.x >> 5);
        int lane  = threadIdx.x & 31;
        if (token >= M) return;

        const float4* xp =
            reinterpret_cast<const float4*>(x + (size_t)token * D_IN);
        float4 v[8];
        float amax = 0.0f;
#pragma unroll
        for (int i = 0; i < 8; i++) {
            v[i] = xp[lane + 32 * i];
            amax = fmaxf(amax, fmaxf(fmaxf(fabsf(v[i].x), fabsf(v[i].y)),
                                     fmaxf(fabsf(v[i].z), fabsf(v[i].w))));
        }
#pragma unroll
        for (int off = 16; off > 0; off >>= 1)
            amax = fmaxf(amax, __shfl_xor_sync(0xFFFFFFFFu, amax, off));

        float amax_c = fmaxf(amax, 1e-12f);
        float inv = 448.0f / amax_c;
        if (lane == 0) g_xscale[token] = amax_c / 448.0f;

        int r  = token & 127;
        int tg = token >> 7;
        uint32_t off = (uint32_t)(r * 128 + ((4 * lane) ^ ((r & 7) * 16)));
#pragma unroll
        for (int i = 0; i < 8; i++) {
            float4 u = v[i];
            __nv_fp8x2_storage_t lo = __nv_cvt_float2_to_fp8x2(
                make_float2(u.x * inv, u.y * inv), __NV_SATFINITE, __NV_E4M3);
            __nv_fp8x2_storage_t hi = __nv_cvt_float2_to_fp8x2(
                make_float2(u.z * inv, u.w * inv), __NV_SATFINITE, __NV_E4M3);
            *reinterpret_cast<uint32_t*>(
                g_qx + ((size_t)tg * NCH + i) * TILE_BYTES + off) =
                (uint32_t)lo | ((uint32_t)hi << 16);
        }
        return;
    }

    // ---------------- weight prep role (with per-block dtype detect) -------
    __shared__ int cf, cb;
    if (threadIdx.x == 0) { cf = 0; cb = 0; }
    __syncthreads();
    {
        const float* wf = (const float*)w;
        const __nv_bfloat16* wb = (const __nv_bfloat16*)w;
        int okf = 0, okb = 0;
        for (int i = threadIdx.x; i < 2048; i += 256) {
            float v = wf[i];
            if (isfinite(v) && fabsf(v) <= 448.0f) okf++;
        }
        for (int i = threadIdx.x; i < 4096; i += 256) {
            float u = __bfloat162float(wb[i]);
            if (isfinite(u) && fabsf(u) <= 448.0f) okb++;
        }
        atomicAdd(&cf, okf);
        atomicAdd(&cb, okb);
    }
    __syncthreads();
    int mode = (cf >= 1946) ? 0 : ((cb >= 3891) ? 1 : 2);

    int i = (blockIdx.x - NQBLK) * 256 + threadIdx.x;   // quad index (4 vals)

    uchar4 q;
    if (mode == 0) {
        float4 v = ((const float4*)w)[i];
        __nv_fp8x2_storage_t lo = __nv_cvt_float2_to_fp8x2(
            make_float2(v.x, v.y), __NV_SATFINITE, __NV_E4M3);
        __nv_fp8x2_storage_t hi = __nv_cvt_float2_to_fp8x2(
            make_float2(v.z, v.w), __NV_SATFINITE, __NV_E4M3);
        q.x = (unsigned char)(lo & 0xFF); q.y = (unsigned char)(lo >> 8);
        q.z = (unsigned char)(hi & 0xFF); q.w = (unsigned char)(hi >> 8);
    } else if (mode == 1) {
        const __nv_bfloat162* wb = (const __nv_bfloat162*)w;
        __nv_bfloat162 p0 = wb[i * 2];
        __nv_bfloat162 p1 = wb[i * 2 + 1];
        __nv_fp8x2_storage_t lo = __nv_cvt_float2_to_fp8x2(
            make_float2(__bfloat162float(p0.x), __bfloat162float(p0.y)),
            __NV_SATFINITE, __NV_E4M3);
        __nv_fp8x2_storage_t hi = __nv_cvt_float2_to_fp8x2(
            make_float2(__bfloat162float(p1.x), __bfloat162float(p1.y)),
            __NV_SATFINITE, __NV_E4M3);
        q.x = (unsigned char)(lo & 0xFF); q.y = (unsigned char)(lo >> 8);
        q.z = (unsigned char)(hi & 0xFF); q.w = (unsigned char)(hi >> 8);
    } else {
        q = ((const uchar4*)w)[i];
    }

    // scatter into tile-major swizzled image
    int b  = i * 4;             // linear byte index in [D_OUT][D_IN]
    int n  = b >> 10;           // weight row
    int k  = b & 1023;
    int kc = k >> 7;
    int c  = k & 127;
    int r  = n & 127;
    int ng = n >> 7;
    uint32_t off = (uint32_t)(r * 128 + (c ^ ((r & 7) * 16)));
    *reinterpret_cast<uchar4*>(
        g_qw + ((size_t)ng * NCH + kc) * TILE_BYTES + off) = q;
}

// ============================================================================
// Kernel 2: fp8 GEMM — exact R9 structure (best measured: 177.5 us).
//   bulk-copy loader + mbarrier full-waits + __syncthreads WAR protection,
//   4 warps (64x64 warp tiles), 3-stage pipeline, 2 CTAs/SM.
// ============================================================================

__global__ void __launch_bounds__(THREADS, 2) fp8ld_gemm_kernel(
    const float* __restrict__ wscale_p,
    const float* __restrict__ bias,
    float* __restrict__ out,
    int M)
{
    extern __shared__ char smem[];
    uint32_t sb = smem_to_u32(smem);
    uint32_t mb = sb;                    // 3 mbarriers at +0, +8, +16
    uint32_t tiles = sb + SMEM_TILES;
    int tid = threadIdx.x;
    int wid = tid >> 5;
    int L   = tid & 31;
    int wm  = wid >> 1;
    int wn  = wid & 1;
    int n0  = blockIdx.x * TILE_N;
    int m0  = blockIdx.y * TILE_M;
    int mg  = m0 >> 7;
    int ng  = n0 >> 7;

    if (tid == 0) {
#pragma unroll
        for (int s = 0; s < STAGES; s++) MBARRIER_INIT(mb + 8 * s, 1);
    }
    __syncthreads();

    // Prologue: issue chunks 0 and 1
    if (tid == 0) {
#pragma unroll
        for (int p = 0; p < 2; p++) {
            uint32_t m = mb + 8 * p;
            uint32_t dst = tiles + p * STAGE_BYTES;
            MBARRIER_EXPECT_TX(m, STAGE_BYTES);
            bulk_g2s(dst, g_qx + ((size_t)mg * NCH + p) * TILE_BYTES,
                     TILE_BYTES, m);
            bulk_g2s(dst + TILE_BYTES, g_qw + ((size_t)ng * NCH + p) * TILE_BYTES,
                     TILE_BYTES, m);
        }
    }

    float d[4][8][4];
#pragma unroll
    for (int i = 0; i < 4; i++)
#pragma unroll
        for (int j = 0; j < 8; j++)
#pragma unroll
            for (int r = 0; r < 4; r++) d[i][j][r] = 0.0f;

    uint32_t a_off = SWZ((uint32_t)(
        (wm * 64 + ((L >> 3) & 1) * 8 + (L & 7)) * KCH + (L >> 4) * 16));
    uint32_t b_off = SWZ((uint32_t)(
        (wn * 64 + (L >> 4) * 8 + (L & 7)) * KCH + ((L >> 3) & 1) * 16));

    int ph0 = 0, ph1 = 0, ph2 = 0;

#pragma unroll 1
    for (int kc = 0; kc < NCH; kc++) {
        int s = kc % STAGES;
        if      (s == 0) { MBARRIER_WAIT_PARITY(mb + 0,  ph0); ph0 ^= 1; }
        else if (s == 1) { MBARRIER_WAIT_PARITY(mb + 8,  ph1); ph1 ^= 1; }
        else             { MBARRIER_WAIT_PARITY(mb + 16, ph2); ph2 ^= 1; }
        // All threads past wait[kc] => all finished computing chunk kc-1,
        // so stage (kc+2)%3 == (kc-1)%3 is reusable after this barrier.
        __syncthreads();
        if (kc + 2 < NCH && tid == 0) {
            int s2 = (kc + 2) % STAGES;
            uint32_t m = mb + 8 * s2;
            uint32_t dst = tiles + s2 * STAGE_BYTES;
            MBARRIER_EXPECT_TX(m, STAGE_BYTES);
            bulk_g2s(dst, g_qx + ((size_t)mg * NCH + kc + 2) * TILE_BYTES,
                     TILE_BYTES, m);
            bulk_g2s(dst + TILE_BYTES,
                     g_qw + ((size_t)ng * NCH + kc + 2) * TILE_BYTES,
                     TILE_BYTES, m);
        }

        uint32_t a_base = tiles + s * STAGE_BYTES + a_off;
        uint32_t b_base = tiles + s * STAGE_BYTES + TILE_BYTES + b_off;

        // SWZ(x + ks*32) == SWZ(x) ^ (ks*32): ks*32 only touches bits [5:6].
#pragma unroll
        for (int ks = 0; ks < 4; ks++) {
            uint32_t kx = (uint32_t)(ks * 32);
            uint32_t bfr[4][4];
#pragma unroll
            for (int t = 0; t < 4; t++)
                ldmatrix_x4(bfr[t], (b_base + (uint32_t)(t * 16 * KCH)) ^ kx);
#pragma unroll
            for (int i = 0; i < 4; i++) {
                uint32_t a[4];
                ldmatrix_x4(a, (a_base + (uint32_t)(i * 16 * KCH)) ^ kx);
#pragma unroll
                for (int t = 0; t < 4; t++) {
                    mma_fp8(d[i][2 * t + 0], a, bfr[t][0], bfr[t][1]);
                    mma_fp8(d[i][2 * t + 1], a, bfr[t][2], bfr[t][3]);
                }
            }
        }
    }

    // Epilogue: out = d * x_scale[m] * w_scale + bias[n]
    float wsc = *wscale_p;
    int ncol0 = n0 + wn * 64;
#pragma unroll
    for (int i = 0; i < 4; i++) {
        int mlo = m0 + wm * 64 + i * 16 + (L >> 2);
        float xs0 = g_xscale[mlo]     * wsc;
        float xs1 = g_xscale[mlo + 8] * wsc;
        float* r0 = out + (size_t)mlo * D_OUT + ncol0;
        float* r1 = r0 + (size_t)8 * D_OUT;
#pragma unroll
        for (int j = 0; j < 8; j++) {
            int c = j * 8 + (L & 3) * 2;
            float b0 = bias[ncol0 + c];
            float b1 = bias[ncol0 + c + 1];
            float2 lo = make_float2(d[i][j][0] * xs0 + b0, d[i][j][1] * xs0 + b1);
            float2 hi = make_float2(d[i][j][2] * xs1 + b0, d[i][j][3] * xs1 + b1);
            *reinterpret_cast<float2*>(r0 + c) = lo;
            *reinterpret_cast<float2*>(r1 + c) = hi;
        }
    }
}

// ============================================================================
// Launch
// ============================================================================

extern "C" void kernel_launch(void* const* d_in, const int* in_sizes, int n_in,
                              void* d_out, int out_size)
{
    const float* x      = (const float*)d_in[0];
    const void*  weight = (const void*)d_in[1];   // dtype probed at runtime
    const float* wscale = (const float*)d_in[2];
    const float* bias   = (const float*)d_in[3];
    float*       out    = (float*)d_out;

    int M = in_sizes[0] / D_IN;   // 32768

    fp8ld_prep_kernel<<<NQBLK + NPBLK, 256>>>(x, weight, M);

    cudaFuncSetAttribute(fp8ld_gemm_kernel,
                         cudaFuncAttributeMaxDynamicSharedMemorySize, SMEM_ALLOC);
    dim3 grid(D_OUT / TILE_N, M / TILE_M);   // (8, 256)
    fp8ld_gemm_kernel<<<grid, THREADS, SMEM_ALLOC>>>(wscale, bias, out, M);
}

// round 14
// speedup vs baseline: 1.2265x; 1.0074x over previous
#include <cuda_runtime.h>
#include <cuda_bf16.h>
#include <cuda_fp8.h>
#include <cstdint>
#include <math.h>

// ============================================================================
// Problem constants
// ============================================================================

static constexpr int D_IN  = 1024;
static constexpr int D_OUT = 1024;
static constexpr int M_MAX = 32768;

static constexpr int TILE_M = 128;
static constexpr int TILE_N = 64;               // CTA tile: 128 x 64
static constexpr int KCH    = 128;              // K bytes per chunk
static constexpr int NCH    = D_IN / KCH;       // 8 chunks
static constexpr int STAGES = 3;
static constexpr int THREADS = 128;             // 4 warps: 2 (M) x 2 (N), 64x32

static constexpr int TILE_BYTES   = 128 * KCH;            // 16 KB full tile image
static constexpr int A_STAGE      = TILE_M * KCH;         // 16 KB
static constexpr int B_STAGE      = TILE_N * KCH;         // 8 KB
static constexpr int STAGE_BYTES  = A_STAGE + B_STAGE;    // 24 KB
static constexpr int SMEM_TILES   = 1024;
static constexpr int SMEM_ALLOC   = SMEM_TILES + STAGES * STAGE_BYTES;  // 74752

// fused quant/prep kernel split
static constexpr int NQBLK = M_MAX / 8;                   // 4096 quant blocks
static constexpr int NPBLK = (D_OUT * D_IN / 4) / 256;    // 1024 prep blocks

#define SWZ(off) ((off) ^ (((off) >> 3) & 0x70))

// ============================================================================
// Scratch (device globals) — PRE-SWIZZLED tile-major layout:
//   g_qx: [M/128 groups][8 kchunks][16384 B tile image (SW128)]
//   g_qw: [8 ngroups   ][8 kchunks][16384 B tile image (SW128)]
// Row-halves of a tile image are self-contained 8 KB blocks (swizzle uses
// r&7 only), so a 64-row B tile is a contiguous 8 KB bulk copy.
// ============================================================================

__device__ __align__(16) unsigned char g_qx[(size_t)M_MAX * D_IN];
__device__ __align__(16) float g_xscale[M_MAX];
__device__ __align__(16) unsigned char g_qw[(size_t)D_OUT * D_IN];

// ============================================================================
// PTX wrappers (base compute_103-safe)
// ============================================================================

__device__ __forceinline__ uint32_t smem_to_u32(const void* smem_ptr) {
    uint32_t addr;
    asm("{ .reg .u64 tmp; cvta.to.shared.u64 tmp, %1; cvt.u32.u64 %0, tmp; }"
        : "=r"(addr) : "l"(smem_ptr));
    return addr;
}

__device__ __forceinline__ void bulk_g2s(uint32_t dst, const void* src,
                                         uint32_t bytes, uint32_t mbar) {
    asm volatile(
        "cp.async.bulk.shared::cluster.global.mbarrier::complete_tx::bytes "
        "[%0], [%1], %2, [%3];"
        :: "r"(dst), "l"(src), "r"(bytes), "r"(mbar) : "memory");
}

#define MBARRIER_INIT(mbar, count) \
    asm volatile("mbarrier.init.shared.b64 [%0], %1;" \
                 :: "r"((uint32_t)(mbar)), "r"((uint32_t)(count)) : "memory")

#define MBARRIER_EXPECT_TX(mbar, bytes) \
    asm volatile("mbarrier.arrive.expect_tx.shared.b64 _, [%0], %1;" \
                 :: "r"((uint32_t)(mbar)), "r"((uint32_t)(bytes)) : "memory")

#define MBARRIER_WAIT_PARITY(mbar, parity) do { \
    uint32_t _mbar = (uint32_t)(mbar); \
    uint32_t _par  = (uint32_t)(parity); \
    asm volatile( \
        "{\n\t" \
        ".reg .pred P1;\n\t" \
        "WAIT_LOOP_%=:\n\t" \
        "mbarrier.try_wait.parity.acquire.cta.shared::cta.b64 P1, [%0], %1, 0x989680;\n\t" \
        "@P1 bra.uni WAIT_DONE_%=;\n\t" \
        "bra.uni WAIT_LOOP_%=;\n\t" \
        "WAIT_DONE_%=:\n\t" \
        "}" \
        :: "r"(_mbar), "r"(_par) : "memory"); \
} while (0)

__device__ __forceinline__ void ldmatrix_x4(uint32_t* r, uint32_t addr) {
    asm volatile("ldmatrix.sync.aligned.m8n8.x4.shared.b16 {%0,%1,%2,%3}, [%4];"
                 : "=r"(r[0]), "=r"(r[1]), "=r"(r[2]), "=r"(r[3])
                 : "r"(addr));
}

__device__ __forceinline__ void mma_fp8(
    float d[4], const uint32_t a[4], const uint32_t b0, const uint32_t b1)
{
    asm volatile(
        "mma.sync.aligned.m16n8k32.row.col.f32.e4m3.e4m3.f32 "
        "{%0,%1,%2,%3}, {%4,%5,%6,%7}, {%8,%9}, {%0,%1,%2,%3};"
        : "+f"(d[0]), "+f"(d[1]), "+f"(d[2]), "+f"(d[3])
        : "r"(a[0]), "r"(a[1]), "r"(a[2]), "r"(a[3]),
          "r"(b0), "r"(b1));
}

// ============================================================================
// Kernel 1: FUSED quant + weight-prep (independent roles by block range)
// ============================================================================

__global__ void __launch_bounds__(256) fp8ld_prep_kernel(
    const float* __restrict__ x, const void* __restrict__ w, int M)
{
    if (blockIdx.x < NQBLK) {
        // ---------------- quant role ----------------
        int token = blockIdx.x * 8 + (threadIdx.x >> 5);
        int lane  = threadIdx.x & 31;
        if (token >= M) return;

        const float4* xp =
            reinterpret_cast<const float4*>(x + (size_t)token * D_IN);
        float4 v[8];
        float amax = 0.0f;
#pragma unroll
        for (int i = 0; i < 8; i++) {
            v[i] = xp[lane + 32 * i];
            amax = fmaxf(amax, fmaxf(fmaxf(fabsf(v[i].x), fabsf(v[i].y)),
                                     fmaxf(fabsf(v[i].z), fabsf(v[i].w))));
        }
#pragma unroll
        for (int off = 16; off > 0; off >>= 1)
            amax = fmaxf(amax, __shfl_xor_sync(0xFFFFFFFFu, amax, off));

        float amax_c = fmaxf(amax, 1e-12f);
        float inv = 448.0f / amax_c;
        if (lane == 0) g_xscale[token] = amax_c / 448.0f;

        int r  = token & 127;
        int tg = token >> 7;
        uint32_t off = (uint32_t)(r * 128 + ((4 * lane) ^ ((r & 7) * 16)));
#pragma unroll
        for (int i = 0; i < 8; i++) {
            float4 u = v[i];
            __nv_fp8x2_storage_t lo = __nv_cvt_float2_to_fp8x2(
                make_float2(u.x * inv, u.y * inv), __NV_SATFINITE, __NV_E4M3);
            __nv_fp8x2_storage_t hi = __nv_cvt_float2_to_fp8x2(
                make_float2(u.z * inv, u.w * inv), __NV_SATFINITE, __NV_E4M3);
            *reinterpret_cast<uint32_t*>(
                g_qx + ((size_t)tg * NCH + i) * TILE_BYTES + off) =
                (uint32_t)lo | ((uint32_t)hi << 16);
        }
        return;
    }

    // ---------------- weight prep role (with per-block dtype detect) -------
    __shared__ int cf, cb;
    if (threadIdx.x == 0) { cf = 0; cb = 0; }
    __syncthreads();
    {
        const float* wf = (const float*)w;
        const __nv_bfloat16* wb = (const __nv_bfloat16*)w;
        int okf = 0, okb = 0;
        for (int i = threadIdx.x; i < 2048; i += 256) {
            float v = wf[i];
            if (isfinite(v) && fabsf(v) <= 448.0f) okf++;
        }
        for (int i = threadIdx.x; i < 4096; i += 256) {
            float u = __bfloat162float(wb[i]);
            if (isfinite(u) && fabsf(u) <= 448.0f) okb++;
        }
        atomicAdd(&cf, okf);
        atomicAdd(&cb, okb);
    }
    __syncthreads();
    int mode = (cf >= 1946) ? 0 : ((cb >= 3891) ? 1 : 2);

    int i = (blockIdx.x - NQBLK) * 256 + threadIdx.x;   // quad index (4 vals)

    uchar4 q;
    if (mode == 0) {
        float4 v = ((const float4*)w)[i];
        __nv_fp8x2_storage_t lo = __nv_cvt_float2_to_fp8x2(
            make_float2(v.x, v.y), __NV_SATFINITE, __NV_E4M3);
        __nv_fp8x2_storage_t hi = __nv_cvt_float2_to_fp8x2(
            make_float2(v.z, v.w), __NV_SATFINITE, __NV_E4M3);
        q.x = (unsigned char)(lo & 0xFF); q.y = (unsigned char)(lo >> 8);
        q.z = (unsigned char)(hi & 0xFF); q.w = (unsigned char)(hi >> 8);
    } else if (mode == 1) {
        const __nv_bfloat162* wb = (const __nv_bfloat162*)w;
        __nv_bfloat162 p0 = wb[i * 2];
        __nv_bfloat162 p1 = wb[i * 2 + 1];
        __nv_fp8x2_storage_t lo = __nv_cvt_float2_to_fp8x2(
            make_float2(__bfloat162float(p0.x), __bfloat162float(p0.y)),
            __NV_SATFINITE, __NV_E4M3);
        __nv_fp8x2_storage_t hi = __nv_cvt_float2_to_fp8x2(
            make_float2(__bfloat162float(p1.x), __bfloat162float(p1.y)),
            __NV_SATFINITE, __NV_E4M3);
        q.x = (unsigned char)(lo & 0xFF); q.y = (unsigned char)(lo >> 8);
        q.z = (unsigned char)(hi & 0xFF); q.w = (unsigned char)(hi >> 8);
    } else {
        q = ((const uchar4*)w)[i];
    }

    // scatter into tile-major swizzled image
    int b  = i * 4;             // linear byte index in [D_OUT][D_IN]
    int n  = b >> 10;           // weight row
    int k  = b & 1023;
    int kc = k >> 7;
    int c  = k & 127;
    int r  = n & 127;
    int ng = n >> 7;
    uint32_t off = (uint32_t)(r * 128 + (c ^ ((r & 7) * 16)));
    *reinterpret_cast<uchar4*>(
        g_qw + ((size_t)ng * NCH + kc) * TILE_BYTES + off) = q;
}

// ============================================================================
// Kernel 2: fp8 GEMM — CTA tile 128x64, 4 warps (64x32 each, 2Mx2N),
//   3-stage bulk-copy pipeline (24 KB/stage), 3 CTAs/SM (12 warps/SM).
//   32 accumulator regs/thread under a 170-reg cap: no spill pressure.
// ============================================================================

__global__ void __launch_bounds__(THREADS, 3) fp8ld_gemm_kernel(
    const float* __restrict__ wscale_p,
    const float* __restrict__ bias,
    float* __restrict__ out,
    int M)
{
    extern __shared__ char smem[];
    uint32_t sb = smem_to_u32(smem);
    uint32_t mb = sb;                    // 3 mbarriers at +0, +8, +16
    uint32_t tiles = sb + SMEM_TILES;
    int tid = threadIdx.x;
    int wid = tid >> 5;
    int L   = tid & 31;
    int wm  = wid >> 1;       // 0..1 (M): 64 rows
    int wn  = wid & 1;        // 0..1 (N): 32 cols
    int n0  = blockIdx.x * TILE_N;      // 0..960 step 64
    int m0  = blockIdx.y * TILE_M;
    int mg  = m0 >> 7;
    int ng  = n0 >> 7;                  // 128-row weight group
    uint32_t nh = ((uint32_t)(n0 >> 6) & 1) * 8192;   // half-tile byte offset

    if (tid == 0) {
#pragma unroll
        for (int s = 0; s < STAGES; s++) MBARRIER_INIT(mb + 8 * s, 1);
    }
    __syncthreads();

    // Prologue: issue chunks 0 and 1
    if (tid == 0) {
#pragma unroll
        for (int p = 0; p < 2; p++) {
            uint32_t m = mb + 8 * p;
            uint32_t dst = tiles + p * STAGE_BYTES;
            MBARRIER_EXPECT_TX(m, STAGE_BYTES);
            bulk_g2s(dst, g_qx + ((size_t)mg * NCH + p) * TILE_BYTES,
                     A_STAGE, m);
            bulk_g2s(dst + A_STAGE,
                     g_qw + ((size_t)ng * NCH + p) * TILE_BYTES + nh,
                     B_STAGE, m);
        }
    }

    float d[4][4][4];
#pragma unroll
    for (int i = 0; i < 4; i++)
#pragma unroll
        for (int j = 0; j < 4; j++)
#pragma unroll
            for (int r = 0; r < 4; r++) d[i][j][r] = 0.0f;

    // A x4 tiles: [r0-7,k0-15][r8-15,k0-15][r0-7,k16-31][r8-15,k16-31]
    uint32_t a_off = SWZ((uint32_t)(
        (wm * 64 + ((L >> 3) & 1) * 8 + (L & 7)) * KCH + (L >> 4) * 16));
    // B x4 tiles: [n0-7,k0-15][n0-7,k16-31][n8-15,k0-15][n8-15,k16-31]
    uint32_t b_off = SWZ((uint32_t)(
        (wn * 32 + (L >> 4) * 8 + (L & 7)) * KCH + ((L >> 3) & 1) * 16));

    int ph0 = 0, ph1 = 0, ph2 = 0;

#pragma unroll 1
    for (int kc = 0; kc < NCH; kc++) {
        int s = kc % STAGES;
        if      (s == 0) { MBARRIER_WAIT_PARITY(mb + 0,  ph0); ph0 ^= 1; }
        else if (s == 1) { MBARRIER_WAIT_PARITY(mb + 8,  ph1); ph1 ^= 1; }
        else             { MBARRIER_WAIT_PARITY(mb + 16, ph2); ph2 ^= 1; }
        // All threads past wait[kc] => all finished computing chunk kc-1,
        // so stage (kc+2)%3 == (kc-1)%3 is reusable after this barrier.
        __syncthreads();
        if (kc + 2 < NCH && tid == 0) {
            int s2 = (kc + 2) % STAGES;
            uint32_t m = mb + 8 * s2;
            uint32_t dst = tiles + s2 * STAGE_BYTES;
            MBARRIER_EXPECT_TX(m, STAGE_BYTES);
            bulk_g2s(dst, g_qx + ((size_t)mg * NCH + kc + 2) * TILE_BYTES,
                     A_STAGE, m);
            bulk_g2s(dst + A_STAGE,
                     g_qw + ((size_t)ng * NCH + kc + 2) * TILE_BYTES + nh,
                     B_STAGE, m);
        }

        uint32_t a_base = tiles + s * STAGE_BYTES + a_off;
        uint32_t b_base = tiles + s * STAGE_BYTES + A_STAGE + b_off;

        // SWZ(x + ks*32) == SWZ(x) ^ (ks*32): ks*32 only touches bits [5:6].
#pragma unroll
        for (int ks = 0; ks < 4; ks++) {
            uint32_t kx = (uint32_t)(ks * 32);
            uint32_t b0[4], b1[4];                    // 32 N-cols of B
            ldmatrix_x4(b0, b_base ^ kx);             // n0-15
            ldmatrix_x4(b1, (b_base + (uint32_t)(16 * KCH)) ^ kx);  // n16-31
#pragma unroll
            for (int i = 0; i < 4; i++) {             // 4 x 16 M-rows of A
                uint32_t a[4];
                ldmatrix_x4(a, (a_base + (uint32_t)(i * 16 * KCH)) ^ kx);
                mma_fp8(d[i][0], a, b0[0], b0[1]);
                mma_fp8(d[i][1], a, b0[2], b0[3]);
                mma_fp8(d[i][2], a, b1[0], b1[1]);
                mma_fp8(d[i][3], a, b1[2], b1[3]);
            }
        }
    }

    // Epilogue: out = d * x_scale[m] * w_scale + bias[n]
    float wsc = *wscale_p;
    int ncol0 = n0 + wn * 32;
#pragma unroll
    for (int i = 0; i < 4; i++) {
        int mlo = m0 + wm * 64 + i * 16 + (L >> 2);
        float xs0 = g_xscale[mlo]     * wsc;
        float xs1 = g_xscale[mlo + 8] * wsc;
        float* r0 = out + (size_t)mlo * D_OUT + ncol0;
        float* r1 = r0 + (size_t)8 * D_OUT;
#pragma unroll
        for (int j = 0; j < 4; j++) {
            int c = j * 8 + (L & 3) * 2;
            float b0 = bias[ncol0 + c];
            float b1 = bias[ncol0 + c + 1];
            float2 lo = make_float2(d[i][j][0] * xs0 + b0, d[i][j][1] * xs0 + b1);
            float2 hi = make_float2(d[i][j][2] * xs1 + b0, d[i][j][3] * xs1 + b1);
            *reinterpret_cast<float2*>(r0 + c) = lo;
            *reinterpret_cast<float2*>(r1 + c) = hi;
        }
    }
}

// ============================================================================
// Launch
// ============================================================================

extern "C" void kernel_launch(void* const* d_in, const int* in_sizes, int n_in,
                              void* d_out, int out_size)
{
    const float* x      = (const float*)d_in[0];
    const void*  weight = (const void*)d_in[1];   // dtype probed at runtime
    const float* wscale = (const float*)d_in[2];
    const float* bias   = (const float*)d_in[3];
    float*       out    = (float*)d_out;

    int M = in_sizes[0] / D_IN;   // 32768

    fp8ld_prep_kernel<<<NQBLK + NPBLK, 256>>>(x, weight, M);

    cudaFuncSetAttribute(fp8ld_gemm_kernel,
                         cudaFuncAttributeMaxDynamicSharedMemorySize, SMEM_ALLOC);
    dim3 grid(D_OUT / TILE_N, M / TILE_M);   // (16, 256)
    fp8ld_gemm_kernel<<<grid, THREADS, SMEM_ALLOC>>>(wscale, bias, out, M);
}